// round 11
// baseline (speedup 1.0000x reference)
#include <cuda_runtime.h>
#include <cuda_fp16.h>
#include <math.h>

#define T_TOK 4096   // B*L tokens
#define DDIM  2048   // hidden dim
#define NEXP  8      // experts
#define IMOE  768    // expert intermediate
#define ISH   4096   // shared expert intermediate

// ---------------- device scratch (static, no allocations) ----------------
__device__ __half g_act_shared[(size_t)T_TOK * ISH];
__device__ __half g_act_moe[(size_t)NEXP * T_TOK * IMOE];
__device__ int    g_idx[NEXP * T_TOK];
__device__ float  g_cw[NEXP * T_TOK];
__device__ int    g_cnt[NEXP];
__device__ float  g_sgate[T_TOK];
// fp16-converted operands
__device__ __half g_h_h[(size_t)T_TOK * DDIM];
__device__ __half g_gup_h[(size_t)NEXP * 2 * IMOE * DDIM];
__device__ __half g_dwn_h[(size_t)NEXP * DDIM * IMOE];
__device__ __half g_sgw_h[(size_t)ISH * DDIM];
__device__ __half g_suw_h[(size_t)ISH * DDIM];
__device__ __half g_sdw_h[(size_t)DDIM * ISH];

// ---------------- helpers ----------------
__device__ __forceinline__ float silu_f(float x) { return x / (1.f + expf(-x)); }

__device__ __forceinline__ void ldsm4(unsigned& r0, unsigned& r1,
                                      unsigned& r2, unsigned& r3, unsigned addr) {
    asm volatile("ldmatrix.sync.aligned.m8n8.x4.shared.b16 {%0,%1,%2,%3}, [%4];"
                 : "=r"(r0), "=r"(r1), "=r"(r2), "=r"(r3) : "r"(addr));
}
__device__ __forceinline__ void mma16(float* c, const unsigned* a, const unsigned* b) {
    asm volatile("mma.sync.aligned.m16n8k16.row.col.f32.f16.f16.f32 "
                 "{%0,%1,%2,%3}, {%4,%5,%6,%7}, {%8,%9}, {%0,%1,%2,%3};"
                 : "+f"(c[0]), "+f"(c[1]), "+f"(c[2]), "+f"(c[3])
                 : "r"(a[0]), "r"(a[1]), "r"(a[2]), "r"(a[3]),
                   "r"(b[0]), "r"(b[1]));
}
__device__ __forceinline__ void cp16(unsigned dst, const void* src) {
    asm volatile("cp.async.cg.shared.global [%0], [%1], 16;"
                 :: "r"(dst), "l"(src) : "memory");
}
__device__ __forceinline__ void cp16z(unsigned dst, const void* src, int sz) {
    asm volatile("cp.async.cg.shared.global [%0], [%1], 16, %2;"
                 :: "r"(dst), "l"(src), "r"(sz) : "memory");
}
#define CP_COMMIT() asm volatile("cp.async.commit_group;" ::: "memory")
#define CP_WAIT1()  asm volatile("cp.async.wait_group 1;" ::: "memory")
#define CP_WAIT0()  asm volatile("cp.async.wait_group 0;" ::: "memory")

__device__ __forceinline__ void red2(float* a, float x, float y) {
    asm volatile("red.global.add.v2.f32 [%0], {%1,%2};"
                 :: "l"(a), "f"(x), "f"(y) : "memory");
}

// XOR-swizzled 16B-chunk index for a [rows x 128B] tile (8 chunks/row)
__device__ __forceinline__ int swz(int row, int chunk) {
    return row * 8 + (chunk ^ (row & 7));
}

// ---------------- small kernels ----------------
__global__ void zero_cnt_kernel() {
    if (threadIdx.x < NEXP) g_cnt[threadIdx.x] = 0;
}

// Fused prep: grid (4096, 7). y<6 = fp16 conversion slices; y==6 = router.
__global__ void prep_kernel(const float* __restrict__ h,
                            const float* __restrict__ gup,
                            const float* __restrict__ dwn,
                            const float* __restrict__ sgw,
                            const float* __restrict__ suw,
                            const float* __restrict__ sdw,
                            const float* __restrict__ gw,
                            const float* __restrict__ segw) {
    const int tid = threadIdx.x;   // 256
    if (blockIdx.y < 6) {
        const float4* src; uint2* dst; size_t n4;
        switch (blockIdx.y) {
            case 0: src=(const float4*)h;   dst=(uint2*)g_h_h;   n4=(size_t)T_TOK*DDIM/4; break;
            case 1: src=(const float4*)gup; dst=(uint2*)g_gup_h; n4=(size_t)NEXP*2*IMOE*DDIM/4; break;
            case 2: src=(const float4*)dwn; dst=(uint2*)g_dwn_h; n4=(size_t)NEXP*DDIM*IMOE/4; break;
            case 3: src=(const float4*)sgw; dst=(uint2*)g_sgw_h; n4=(size_t)ISH*DDIM/4; break;
            case 4: src=(const float4*)suw; dst=(uint2*)g_suw_h; n4=(size_t)ISH*DDIM/4; break;
            default:src=(const float4*)sdw; dst=(uint2*)g_sdw_h; n4=(size_t)DDIM*ISH/4; break;
        }
        size_t i = (size_t)blockIdx.x * 256 + tid;
        size_t stride = (size_t)gridDim.x * 256;
        for (; i < n4; i += stride) {
            float4 v = src[i];
            __half2 lo = __floats2half2_rn(v.x, v.y);
            __half2 hi = __floats2half2_rn(v.z, v.w);
            uint2 q;
            q.x = *(unsigned*)&lo;
            q.y = *(unsigned*)&hi;
            dst[i] = q;
        }
        return;
    }
    // ---- router ----
    const int t = blockIdx.x;
    float acc[9];
#pragma unroll
    for (int e = 0; e < 9; e++) acc[e] = 0.f;
    const float* hp = h + (size_t)t * DDIM;
    for (int d = tid; d < DDIM; d += 256) {
        float hv = hp[d];
#pragma unroll
        for (int e = 0; e < 8; e++) acc[e] += hv * gw[e * DDIM + d];
        acc[8] += hv * segw[d];
    }
#pragma unroll
    for (int e = 0; e < 9; e++) {
#pragma unroll
        for (int off = 16; off > 0; off >>= 1)
            acc[e] += __shfl_down_sync(0xffffffffu, acc[e], off);
    }
    __shared__ float s[9][8];
    int warp = tid >> 5, lane = tid & 31;
    if (lane == 0) {
#pragma unroll
        for (int e = 0; e < 9; e++) s[e][warp] = acc[e];
    }
    __syncthreads();
    if (tid == 0) {
        float logits[9];
#pragma unroll
        for (int e = 0; e < 9; e++) {
            float v = 0.f;
#pragma unroll
            for (int w2 = 0; w2 < 8; w2++) v += s[e][w2];
            logits[e] = v;
        }
        int i1 = 0; float l1 = logits[0];
#pragma unroll
        for (int e = 1; e < 8; e++)
            if (logits[e] > l1) { l1 = logits[e]; i1 = e; }
        int i2 = -1; float l2 = -3.0e38f;
#pragma unroll
        for (int e = 0; e < 8; e++)
            if (e != i1 && logits[e] > l2) { l2 = logits[e]; i2 = e; }
        float w1 = 1.f / (1.f + expf(l2 - l1));
        float w2 = 1.f - w1;
        int r1 = atomicAdd(&g_cnt[i1], 1);
        g_idx[i1 * T_TOK + r1] = t;  g_cw[i1 * T_TOK + r1] = w1;
        int r2 = atomicAdd(&g_cnt[i2], 1);
        g_idx[i2 * T_TOK + r2] = t;  g_cw[i2 * T_TOK + r2] = w2;
        g_sgate[t] = 1.f / (1.f + expf(-logits[8]));
    }
}

// ============= fused gate/up GEMM (fp16, 128M x 128N per matrix, 512 thr) =============
// 1D grid: [0,1024) shared (32 m x 32 n), [1024,2560) MoE (e=r/192; 32 m x 6 n).
// Warps 4(M) x 4(N): warp tile 32x32 per matrix (G and U), 64 accum regs.
// K-stage = 64 halfs (128 B/row). Stage: [A 16KB][G 16KB][U 16KB]=48KB; 3 stages = 144KB.
__global__ void __launch_bounds__(512, 1)
gateup_fused()
{
    extern __shared__ unsigned smem[];
    const int bid = blockIdx.x;
    const bool gather = (bid >= 1024);
    int e = 0, my, nx;
    if (!gather) { my = bid >> 5; nx = bid & 31; }
    else { int r = bid - 1024; e = r / 192; int q = r % 192; my = q / 6; nx = q % 6; }

    const int M  = gather ? g_cnt[e] : T_TOK;
    const int m0 = my * 128;
    if (m0 >= M) return;
    const int n0 = nx * 128;

    const __half *Bg, *Bu; __half* C; int ldc;
    if (gather) {
        Bg = g_gup_h + (size_t)e * 2 * IMOE * DDIM;
        Bu = Bg + (size_t)IMOE * DDIM;
        C  = g_act_moe + (size_t)e * T_TOK * IMOE;  ldc = IMOE;
    } else {
        Bg = g_sgw_h;  Bu = g_suw_h;
        C  = g_act_shared;  ldc = ISH;
    }

    const unsigned sbase = (unsigned)__cvta_generic_to_shared(smem);
    const int tid = threadIdx.x, lane = tid & 31, wid = tid >> 5;
    const int wm = (wid & 3) * 32, wn = (wid >> 2) * 32;

    // cp.async: A 128 rows (2 chunks/thread), G 128 rows (2), U 128 rows (2)
    const __half* asrc[2]; int asz[2]; unsigned adst[2];
    const __half* gsrc[2]; const __half* usrc[2]; unsigned bdst[2];
#pragma unroll
    for (int i = 0; i < 2; i++) {
        int id = tid + i * 512, row = id >> 3, ch = id & 7;
        int r = m0 + row;
        bool v = gather ? (r < M) : true;
        const __half* arow;
        if (gather) arow = v ? g_h_h + (size_t)g_idx[e * T_TOK + r] * DDIM : g_h_h;
        else        arow = g_h_h + (size_t)r * DDIM;
        asrc[i] = arow + ch * 8;
        asz[i]  = v ? 16 : 0;
        adst[i] = swz(row, ch) * 16;
        gsrc[i] = Bg + (size_t)(n0 + row) * DDIM + ch * 8;
        usrc[i] = Bu + (size_t)(n0 + row) * DDIM + ch * 8;
        bdst[i] = swz(row, ch) * 16;
    }

    auto issue = [&](int s) {
        unsigned sb = sbase + (s % 3) * 49152;
        int koff = s * 64;
#pragma unroll
        for (int i = 0; i < 2; i++) cp16z(sb + adst[i], asrc[i] + koff, asz[i]);
#pragma unroll
        for (int i = 0; i < 2; i++) cp16(sb + 16384 + bdst[i], gsrc[i] + koff);
#pragma unroll
        for (int i = 0; i < 2; i++) cp16(sb + 32768 + bdst[i], usrc[i] + koff);
    };

    // fragment offsets (m16n8k16)
    const int l7 = lane & 7, lb3 = (lane >> 3) & 1, lb4 = lane >> 4;
    unsigned offA[4], offB[4];
#pragma unroll
    for (int ks = 0; ks < 4; ks++) {
        offA[ks] = swz(wm + l7 + lb3 * 8, 2 * ks + lb4) * 16;
        offB[ks] = swz(wn + l7 + lb4 * 8, 2 * ks + lb3) * 16;
    }

    float cg[2][4][4] = {}, cu[2][4][4] = {};
    const int S = DDIM / 64;   // 32

    issue(0); CP_COMMIT();
    issue(1); CP_COMMIT();

#pragma unroll 1
    for (int s = 0; s < S; s++) {
        if (s + 1 < S) { CP_WAIT1(); } else { CP_WAIT0(); }
        __syncthreads();
        unsigned sb = sbase + (s % 3) * 49152;
#pragma unroll
        for (int ks = 0; ks < 4; ks++) {
            unsigned a[2][4], bg[4][2], bu[4][2];
#pragma unroll
            for (int mt = 0; mt < 2; mt++)
                ldsm4(a[mt][0], a[mt][1], a[mt][2], a[mt][3],
                      sb + offA[ks] + mt * 2048);
#pragma unroll
            for (int jg = 0; jg < 2; jg++) {
                ldsm4(bg[2*jg][0], bg[2*jg][1], bg[2*jg+1][0], bg[2*jg+1][1],
                      sb + 16384 + offB[ks] + jg * 2048);
                ldsm4(bu[2*jg][0], bu[2*jg][1], bu[2*jg+1][0], bu[2*jg+1][1],
                      sb + 32768 + offB[ks] + jg * 2048);
            }
#pragma unroll
            for (int mt = 0; mt < 2; mt++)
#pragma unroll
                for (int nt = 0; nt < 4; nt++) {
                    mma16(cg[mt][nt], a[mt], bg[nt]);
                    mma16(cu[mt][nt], a[mt], bu[nt]);
                }
        }
        if (s + 2 < S) { issue(s + 2); CP_COMMIT(); }
    }

    // epilogue: act = fp16(silu(g)*u)
    const int rr2 = lane >> 2, cc = (lane & 3) * 2;
#pragma unroll
    for (int mt = 0; mt < 2; mt++) {
#pragma unroll
        for (int h2 = 0; h2 < 2; h2++) {
            int r = m0 + wm + mt * 16 + rr2 + h2 * 8;
            if (gather && r >= M) continue;
            __half* crow = C + (size_t)r * ldc + n0 + wn;
#pragma unroll
            for (int nt = 0; nt < 4; nt++) {
                float v0 = silu_f(cg[mt][nt][2*h2+0]) * cu[mt][nt][2*h2+0];
                float v1 = silu_f(cg[mt][nt][2*h2+1]) * cu[mt][nt][2*h2+1];
                *(__half2*)(crow + nt * 8 + cc) = __floats2half2_rn(v0, v1);
            }
        }
    }
}

// ============= fused down GEMM (fp16, 128x128 tile; shared first, then MoE) =============
// 1D grid: [0,512) shared (32 m x 16 n, K=4096), [512,4608) MoE (e=r/512; 32 m x 16 n, K=768).
// Block 128M x 128N; warps 4(M) x 2(N): warp tile 32x64.
// K-stage = 64 halfs. Stage: [A 16KB][B 16KB]=32KB; 3 stages = 96KB; 2 CTAs/SM.
__global__ void __launch_bounds__(256, 2)
down_fused(float* __restrict__ out)
{
    extern __shared__ unsigned smem[];
    const int bid = blockIdx.x;
    const bool moe = (bid >= 512);
    int e = 0, my, nx;
    if (!moe) { my = bid >> 4; nx = bid & 15; }
    else { int r = bid - 512; e = r >> 9; int q = r & 511; my = q >> 4; nx = q & 15; }

    const int M  = moe ? g_cnt[e] : T_TOK;
    const int m0 = my * 128;
    if (m0 >= M) return;
    const int n0 = nx * 128;

    const __half* A; int lda; const __half* B; int Kd;
    if (moe) { A = g_act_moe + (size_t)e * T_TOK * IMOE; lda = IMOE;
               B = g_dwn_h  + (size_t)e * DDIM * IMOE;   Kd = IMOE; }
    else     { A = g_act_shared; lda = ISH; B = g_sdw_h; Kd = ISH; }

    const unsigned sbase = (unsigned)__cvta_generic_to_shared(smem);
    const int tid = threadIdx.x, lane = tid & 31, wid = tid >> 5;
    const int wm = (wid & 3) * 32, wn = (wid >> 2) * 64;

    const __half* asrc[4]; int asz[4]; unsigned adst[4];
    const __half* bsrc[4]; unsigned bdst[4];
#pragma unroll
    for (int i = 0; i < 4; i++) {
        int id = tid + i * 256, row = id >> 3, ch = id & 7;
        int r = m0 + row;
        bool v = (r < M);
        asrc[i] = v ? A + (size_t)r * lda + ch * 8 : A;
        asz[i]  = v ? 16 : 0;
        adst[i] = swz(row, ch) * 16;
        bsrc[i] = B + (size_t)(n0 + row) * Kd + ch * 8;
        bdst[i] = 16384 + swz(row, ch) * 16;
    }

    auto issue = [&](int s) {
        unsigned sb = sbase + (s % 3) * 32768;
        int koff = s * 64;
#pragma unroll
        for (int i = 0; i < 4; i++) cp16z(sb + adst[i], asrc[i] + koff, asz[i]);
#pragma unroll
        for (int i = 0; i < 4; i++) cp16(sb + bdst[i], bsrc[i] + koff);
    };

    const int l7 = lane & 7, lb3 = (lane >> 3) & 1, lb4 = lane >> 4;
    unsigned offA[4], offB[4];
#pragma unroll
    for (int ks = 0; ks < 4; ks++) {
        offA[ks] = swz(wm + l7 + lb3 * 8, 2 * ks + lb4) * 16;
        offB[ks] = 16384 + swz(wn + l7 + lb4 * 8, 2 * ks + lb3) * 16;
    }

    float c[2][8][4] = {};
    const int S = Kd / 64;

    issue(0); CP_COMMIT();
    issue(1); CP_COMMIT();

#pragma unroll 1
    for (int s = 0; s < S; s++) {
        if (s + 1 < S) { CP_WAIT1(); } else { CP_WAIT0(); }
        __syncthreads();
        unsigned sb = sbase + (s % 3) * 32768;
#pragma unroll
        for (int ks = 0; ks < 4; ks++) {
            unsigned a[2][4], bb[8][2];
#pragma unroll
            for (int mt = 0; mt < 2; mt++)
                ldsm4(a[mt][0], a[mt][1], a[mt][2], a[mt][3],
                      sb + offA[ks] + mt * 2048);
#pragma unroll
            for (int jg = 0; jg < 4; jg++)
                ldsm4(bb[2*jg][0], bb[2*jg][1], bb[2*jg+1][0], bb[2*jg+1][1],
                      sb + offB[ks] + jg * 2048);
#pragma unroll
            for (int mt = 0; mt < 2; mt++)
#pragma unroll
                for (int nt = 0; nt < 8; nt++)
                    mma16(c[mt][nt], a[mt], bb[nt]);
        }
        if (s + 2 < S) { issue(s + 2); CP_COMMIT(); }
    }

    const int rr2 = lane >> 2, cc = (lane & 3) * 2;
#pragma unroll
    for (int mt = 0; mt < 2; mt++) {
#pragma unroll
        for (int h2 = 0; h2 < 2; h2++) {
            int r = m0 + wm + mt * 16 + rr2 + h2 * 8;
            if (r >= M) continue;
            float wt; float* orow;
            if (moe) {
                int tok = g_idx[e * T_TOK + r];
                wt   = g_cw[e * T_TOK + r];
                orow = out + (size_t)tok * DDIM + n0 + wn;
            } else {
                wt   = g_sgate[r];
                orow = out + (size_t)r * DDIM + n0 + wn;
            }
#pragma unroll
            for (int nt = 0; nt < 8; nt++)
                red2(orow + nt * 8 + cc,
                     wt * c[mt][nt][2*h2+0], wt * c[mt][nt][2*h2+1]);
        }
    }
}

// ---------------- launch ----------------
extern "C" void kernel_launch(void* const* d_in, const int* in_sizes, int n_in,
                              void* d_out, int out_size) {
    const float* h    = (const float*)d_in[0];  // [T, D]
    const float* gw   = (const float*)d_in[1];  // [E, D]
    const float* gup  = (const float*)d_in[2];  // [E, 2I, D]
    const float* dwn  = (const float*)d_in[3];  // [E, D, I]
    const float* sgw  = (const float*)d_in[4];  // [IS, D]
    const float* suw  = (const float*)d_in[5];  // [IS, D]
    const float* sdw  = (const float*)d_in[6];  // [D, IS]
    const float* segw = (const float*)d_in[7];  // [1, D]
    float* out = (float*)d_out;

    const int SMEM_GU = 147456;  // 144KB (3 x 48KB); 1 CTA/SM
    const int SMEM_DN = 98304;   // 96KB (3 x 32KB); 2 CTAs/SM

    static bool init_done = false;
    if (!init_done) {
        cudaFuncSetAttribute(gateup_fused, cudaFuncAttributeMaxDynamicSharedMemorySize, SMEM_GU);
        cudaFuncSetAttribute(down_fused,   cudaFuncAttributeMaxDynamicSharedMemorySize, SMEM_DN);
        init_done = true;
    }

    // zero output (down_fused accumulates atomically into it)
    cudaMemsetAsync(out, 0, (size_t)out_size * sizeof(float));

    zero_cnt_kernel<<<1, 32>>>();

    // fused: fp16 conversion of h + all weights (y<6) and router (y==6)
    prep_kernel<<<dim3(T_TOK, 7), 256>>>(h, gup, dwn, sgw, suw, sdw, gw, segw);

    // fused gate/up (128x128, 512 thr): shared (0..1023) + MoE (1024..2559)
    gateup_fused<<<2560, 512, SMEM_GU>>>();

    // fused down (128x128 tiles): shared (0..511) + MoE (512..4607)
    down_fused<<<4608, 256, SMEM_DN>>>(out);
}

// round 12
// speedup vs baseline: 1.0905x; 1.0905x over previous
#include <cuda_runtime.h>
#include <cuda_fp16.h>
#include <math.h>

#define T_TOK 4096   // B*L tokens
#define DDIM  2048   // hidden dim
#define NEXP  8      // experts
#define IMOE  768    // expert intermediate
#define ISH   4096   // shared expert intermediate

// ---------------- device scratch (static, no allocations) ----------------
__device__ __half g_act_shared[(size_t)T_TOK * ISH];
__device__ __half g_act_moe[(size_t)NEXP * T_TOK * IMOE];
__device__ int    g_idx[NEXP * T_TOK];
__device__ float  g_cw[NEXP * T_TOK];
__device__ int    g_cnt[NEXP];
__device__ float  g_sgate[T_TOK];
// fp16-converted operands
__device__ __half g_h_h[(size_t)T_TOK * DDIM];
__device__ __half g_gup_h[(size_t)NEXP * 2 * IMOE * DDIM];
__device__ __half g_dwn_h[(size_t)NEXP * DDIM * IMOE];
__device__ __half g_sgw_h[(size_t)ISH * DDIM];
__device__ __half g_suw_h[(size_t)ISH * DDIM];
__device__ __half g_sdw_h[(size_t)DDIM * ISH];

// ---------------- helpers ----------------
__device__ __forceinline__ float silu_f(float x) { return x / (1.f + expf(-x)); }

__device__ __forceinline__ void ldsm4(unsigned& r0, unsigned& r1,
                                      unsigned& r2, unsigned& r3, unsigned addr) {
    asm volatile("ldmatrix.sync.aligned.m8n8.x4.shared.b16 {%0,%1,%2,%3}, [%4];"
                 : "=r"(r0), "=r"(r1), "=r"(r2), "=r"(r3) : "r"(addr));
}
__device__ __forceinline__ void mma16(float* c, const unsigned* a, const unsigned* b) {
    asm volatile("mma.sync.aligned.m16n8k16.row.col.f32.f16.f16.f32 "
                 "{%0,%1,%2,%3}, {%4,%5,%6,%7}, {%8,%9}, {%0,%1,%2,%3};"
                 : "+f"(c[0]), "+f"(c[1]), "+f"(c[2]), "+f"(c[3])
                 : "r"(a[0]), "r"(a[1]), "r"(a[2]), "r"(a[3]),
                   "r"(b[0]), "r"(b[1]));
}
__device__ __forceinline__ void cp16(unsigned dst, const void* src) {
    asm volatile("cp.async.cg.shared.global [%0], [%1], 16;"
                 :: "r"(dst), "l"(src) : "memory");
}
__device__ __forceinline__ void cp16z(unsigned dst, const void* src, int sz) {
    asm volatile("cp.async.cg.shared.global [%0], [%1], 16, %2;"
                 :: "r"(dst), "l"(src), "r"(sz) : "memory");
}
#define CP_COMMIT() asm volatile("cp.async.commit_group;" ::: "memory")
#define CP_WAIT1()  asm volatile("cp.async.wait_group 1;" ::: "memory")
#define CP_WAIT0()  asm volatile("cp.async.wait_group 0;" ::: "memory")

__device__ __forceinline__ void red2(float* a, float x, float y) {
    asm volatile("red.global.add.v2.f32 [%0], {%1,%2};"
                 :: "l"(a), "f"(x), "f"(y) : "memory");
}

// XOR-swizzled 16B-chunk index for a [rows x 128B] tile (8 chunks/row)
__device__ __forceinline__ int swz(int row, int chunk) {
    return row * 8 + (chunk ^ (row & 7));
}

// ---------------- small kernels ----------------
__global__ void zero_cnt_kernel() {
    if (threadIdx.x < NEXP) g_cnt[threadIdx.x] = 0;
}

// Fused prep: grid (4096, 7). y<6 = fp16 conversion slices; y==6 = router.
__global__ void prep_kernel(const float* __restrict__ h,
                            const float* __restrict__ gup,
                            const float* __restrict__ dwn,
                            const float* __restrict__ sgw,
                            const float* __restrict__ suw,
                            const float* __restrict__ sdw,
                            const float* __restrict__ gw,
                            const float* __restrict__ segw) {
    const int tid = threadIdx.x;   // 256
    if (blockIdx.y < 6) {
        const float4* src; uint2* dst; size_t n4;
        switch (blockIdx.y) {
            case 0: src=(const float4*)h;   dst=(uint2*)g_h_h;   n4=(size_t)T_TOK*DDIM/4; break;
            case 1: src=(const float4*)gup; dst=(uint2*)g_gup_h; n4=(size_t)NEXP*2*IMOE*DDIM/4; break;
            case 2: src=(const float4*)dwn; dst=(uint2*)g_dwn_h; n4=(size_t)NEXP*DDIM*IMOE/4; break;
            case 3: src=(const float4*)sgw; dst=(uint2*)g_sgw_h; n4=(size_t)ISH*DDIM/4; break;
            case 4: src=(const float4*)suw; dst=(uint2*)g_suw_h; n4=(size_t)ISH*DDIM/4; break;
            default:src=(const float4*)sdw; dst=(uint2*)g_sdw_h; n4=(size_t)DDIM*ISH/4; break;
        }
        size_t i = (size_t)blockIdx.x * 256 + tid;
        size_t stride = (size_t)gridDim.x * 256;
        for (; i < n4; i += stride) {
            float4 v = src[i];
            __half2 lo = __floats2half2_rn(v.x, v.y);
            __half2 hi = __floats2half2_rn(v.z, v.w);
            uint2 q;
            q.x = *(unsigned*)&lo;
            q.y = *(unsigned*)&hi;
            dst[i] = q;
        }
        return;
    }
    // ---- router ----
    const int t = blockIdx.x;
    float acc[9];
#pragma unroll
    for (int e = 0; e < 9; e++) acc[e] = 0.f;
    const float* hp = h + (size_t)t * DDIM;
    for (int d = tid; d < DDIM; d += 256) {
        float hv = hp[d];
#pragma unroll
        for (int e = 0; e < 8; e++) acc[e] += hv * gw[e * DDIM + d];
        acc[8] += hv * segw[d];
    }
#pragma unroll
    for (int e = 0; e < 9; e++) {
#pragma unroll
        for (int off = 16; off > 0; off >>= 1)
            acc[e] += __shfl_down_sync(0xffffffffu, acc[e], off);
    }
    __shared__ float s[9][8];
    int warp = tid >> 5, lane = tid & 31;
    if (lane == 0) {
#pragma unroll
        for (int e = 0; e < 9; e++) s[e][warp] = acc[e];
    }
    __syncthreads();
    if (tid == 0) {
        float logits[9];
#pragma unroll
        for (int e = 0; e < 9; e++) {
            float v = 0.f;
#pragma unroll
            for (int w2 = 0; w2 < 8; w2++) v += s[e][w2];
            logits[e] = v;
        }
        int i1 = 0; float l1 = logits[0];
#pragma unroll
        for (int e = 1; e < 8; e++)
            if (logits[e] > l1) { l1 = logits[e]; i1 = e; }
        int i2 = -1; float l2 = -3.0e38f;
#pragma unroll
        for (int e = 0; e < 8; e++)
            if (e != i1 && logits[e] > l2) { l2 = logits[e]; i2 = e; }
        float w1 = 1.f / (1.f + expf(l2 - l1));
        float w2 = 1.f - w1;
        int r1 = atomicAdd(&g_cnt[i1], 1);
        g_idx[i1 * T_TOK + r1] = t;  g_cw[i1 * T_TOK + r1] = w1;
        int r2 = atomicAdd(&g_cnt[i2], 1);
        g_idx[i2 * T_TOK + r2] = t;  g_cw[i2 * T_TOK + r2] = w2;
        g_sgate[t] = 1.f / (1.f + expf(-logits[8]));
    }
}

// ============= fused gate/up GEMM (fp16, 128 thr, warp tile 64x32 per matrix) =============
// 1D grid: [0,2048) shared (32 m x 64 n-tiles), [2048,5120) MoE (e=r/384; 32 m x 12 n).
// Block 128M x 64N per matrix; 4 warps 2(M) x 2(N): warp tile 64x32 per matrix (G+U).
// K-stage = 64 halfs. Stage: [A 16KB][G 8KB][U 8KB]=32KB; 3 stages = 96KB; 2 CTAs/SM.
__global__ void __launch_bounds__(128, 2)
gateup_fused()
{
    extern __shared__ unsigned smem[];
    const int bid = blockIdx.x;
    const bool gather = (bid >= 2048);
    int e = 0, my, nx;
    if (!gather) { my = bid >> 6; nx = bid & 63; }
    else { int r = bid - 2048; e = r / 384; int q = r % 384; my = q / 12; nx = q % 12; }

    const int M  = gather ? g_cnt[e] : T_TOK;
    const int m0 = my * 128;
    if (m0 >= M) return;
    const int n0 = nx * 64;

    const __half *Bg, *Bu; __half* C; int ldc;
    if (gather) {
        Bg = g_gup_h + (size_t)e * 2 * IMOE * DDIM;
        Bu = Bg + (size_t)IMOE * DDIM;
        C  = g_act_moe + (size_t)e * T_TOK * IMOE;  ldc = IMOE;
    } else {
        Bg = g_sgw_h;  Bu = g_suw_h;
        C  = g_act_shared;  ldc = ISH;
    }

    const unsigned sbase = (unsigned)__cvta_generic_to_shared(smem);
    const int tid = threadIdx.x, lane = tid & 31, wid = tid >> 5;
    const int wm = (wid & 1) * 64, wn = (wid >> 1) * 32;

    // cp.async: A 128 rows (8 chunks/thread, rows row0+16i), G/U 64 rows (4 each)
    const int row0 = tid >> 3, ch = tid & 7;
    const __half* asrc[8]; unsigned amask = 0;
#pragma unroll
    for (int i = 0; i < 8; i++) {
        int r = m0 + row0 + 16 * i;
        bool v = gather ? (r < M) : true;
        const __half* arow;
        if (gather) arow = v ? g_h_h + (size_t)g_idx[e * T_TOK + r] * DDIM : g_h_h;
        else        arow = g_h_h + (size_t)r * DDIM;
        asrc[i] = arow + ch * 8;
        if (v) amask |= (1u << i);
    }
    const unsigned adst0 = swz(row0, ch) * 16;
    const __half* gsrc0 = Bg + (size_t)(n0 + row0) * DDIM + ch * 8;
    const __half* usrc0 = Bu + (size_t)(n0 + row0) * DDIM + ch * 8;

    auto issue = [&](int s) {
        unsigned sb = sbase + (s % 3) * 32768;
        int koff = s * 64;
#pragma unroll
        for (int i = 0; i < 8; i++)
            cp16z(sb + adst0 + i * 2048, asrc[i] + koff, ((amask >> i) & 1) ? 16 : 0);
#pragma unroll
        for (int i = 0; i < 4; i++)
            cp16(sb + 16384 + adst0 + i * 2048, gsrc0 + koff + (size_t)i * 16 * DDIM);
#pragma unroll
        for (int i = 0; i < 4; i++)
            cp16(sb + 24576 + adst0 + i * 2048, usrc0 + koff + (size_t)i * 16 * DDIM);
    };

    // fragment offsets (m16n8k16)
    const int l7 = lane & 7, lb3 = (lane >> 3) & 1, lb4 = lane >> 4;
    unsigned offA[4], offB[4];
#pragma unroll
    for (int ks = 0; ks < 4; ks++) {
        offA[ks] = swz(wm + l7 + lb3 * 8, 2 * ks + lb4) * 16;
        offB[ks] = swz(wn + l7 + lb4 * 8, 2 * ks + lb3) * 16;
    }

    float cg[4][4][4] = {}, cu[4][4][4] = {};
    const int S = DDIM / 64;   // 32

    issue(0); CP_COMMIT();
    issue(1); CP_COMMIT();

#pragma unroll 1
    for (int s = 0; s < S; s++) {
        if (s + 1 < S) { CP_WAIT1(); } else { CP_WAIT0(); }
        __syncthreads();
        unsigned sb = sbase + (s % 3) * 32768;
#pragma unroll
        for (int ks = 0; ks < 4; ks++) {
            unsigned a[4][4], bg[4][2], bu[4][2];
#pragma unroll
            for (int mt = 0; mt < 4; mt++)
                ldsm4(a[mt][0], a[mt][1], a[mt][2], a[mt][3],
                      sb + offA[ks] + mt * 2048);
#pragma unroll
            for (int jg = 0; jg < 2; jg++) {
                ldsm4(bg[2*jg][0], bg[2*jg][1], bg[2*jg+1][0], bg[2*jg+1][1],
                      sb + 16384 + offB[ks] + jg * 2048);
                ldsm4(bu[2*jg][0], bu[2*jg][1], bu[2*jg+1][0], bu[2*jg+1][1],
                      sb + 24576 + offB[ks] + jg * 2048);
            }
#pragma unroll
            for (int mt = 0; mt < 4; mt++)
#pragma unroll
                for (int nt = 0; nt < 4; nt++) {
                    mma16(cg[mt][nt], a[mt], bg[nt]);
                    mma16(cu[mt][nt], a[mt], bu[nt]);
                }
        }
        if (s + 2 < S) { issue(s + 2); CP_COMMIT(); }
    }

    // epilogue: act = fp16(silu(g)*u)
    const int rr2 = lane >> 2, cc = (lane & 3) * 2;
#pragma unroll
    for (int mt = 0; mt < 4; mt++) {
#pragma unroll
        for (int h2 = 0; h2 < 2; h2++) {
            int r = m0 + wm + mt * 16 + rr2 + h2 * 8;
            if (gather && r >= M) continue;
            __half* crow = C + (size_t)r * ldc + n0 + wn;
#pragma unroll
            for (int nt = 0; nt < 4; nt++) {
                float v0 = silu_f(cg[mt][nt][2*h2+0]) * cu[mt][nt][2*h2+0];
                float v1 = silu_f(cg[mt][nt][2*h2+1]) * cu[mt][nt][2*h2+1];
                *(__half2*)(crow + nt * 8 + cc) = __floats2half2_rn(v0, v1);
            }
        }
    }
}

// ============= fused down GEMM (fp16, 128 thr, warp tile 64x64) =============
// 1D grid: [0,512) shared (32 m x 16 n, K=4096), [512,4608) MoE (e=r/512; 32 m x 16 n, K=768).
// Block 128M x 128N; 4 warps 2(M) x 2(N): warp tile 64x64 (128 accum regs).
// K-stage = 64 halfs. Stage: [A 16KB][B 16KB]=32KB; 3 stages = 96KB; 2 CTAs/SM.
__global__ void __launch_bounds__(128, 2)
down_fused(float* __restrict__ out)
{
    extern __shared__ unsigned smem[];
    const int bid = blockIdx.x;
    const bool moe = (bid >= 512);
    int e = 0, my, nx;
    if (!moe) { my = bid >> 4; nx = bid & 15; }
    else { int r = bid - 512; e = r >> 9; int q = r & 511; my = q >> 4; nx = q & 15; }

    const int M  = moe ? g_cnt[e] : T_TOK;
    const int m0 = my * 128;
    if (m0 >= M) return;
    const int n0 = nx * 128;

    const __half* A; int lda; const __half* B; int Kd;
    if (moe) { A = g_act_moe + (size_t)e * T_TOK * IMOE; lda = IMOE;
               B = g_dwn_h  + (size_t)e * DDIM * IMOE;   Kd = IMOE; }
    else     { A = g_act_shared; lda = ISH; B = g_sdw_h; Kd = ISH; }

    const unsigned sbase = (unsigned)__cvta_generic_to_shared(smem);
    const int tid = threadIdx.x, lane = tid & 31, wid = tid >> 5;
    const int wm = (wid & 1) * 64, wn = (wid >> 1) * 64;

    // cp.async: A 128 rows (8 chunks, rows row0+16i, contiguous slots),
    //           B 128 rows (8 chunks)
    const int row0 = tid >> 3, ch = tid & 7;
    const __half* asrc0 = A + (size_t)(m0 + row0) * lda + ch * 8;
    const __half* bsrc0 = B + (size_t)(n0 + row0) * Kd + ch * 8;
    const unsigned adst0 = swz(row0, ch) * 16;

    auto issue = [&](int s) {
        unsigned sb = sbase + (s % 3) * 32768;
        int koff = s * 64;
#pragma unroll
        for (int i = 0; i < 8; i++) {
            int sz = (m0 + row0 + 16 * i < M) ? 16 : 0;
            cp16z(sb + adst0 + i * 2048, asrc0 + koff + (size_t)i * 16 * lda, sz);
        }
#pragma unroll
        for (int i = 0; i < 8; i++)
            cp16(sb + 16384 + adst0 + i * 2048, bsrc0 + koff + (size_t)i * 16 * Kd);
    };

    const int l7 = lane & 7, lb3 = (lane >> 3) & 1, lb4 = lane >> 4;
    unsigned offA[4], offB[4];
#pragma unroll
    for (int ks = 0; ks < 4; ks++) {
        offA[ks] = swz(wm + l7 + lb3 * 8, 2 * ks + lb4) * 16;
        offB[ks] = 16384 + swz(wn + l7 + lb4 * 8, 2 * ks + lb3) * 16;
    }

    float c[4][8][4] = {};
    const int S = Kd / 64;

    issue(0); CP_COMMIT();
    issue(1); CP_COMMIT();

#pragma unroll 1
    for (int s = 0; s < S; s++) {
        if (s + 1 < S) { CP_WAIT1(); } else { CP_WAIT0(); }
        __syncthreads();
        unsigned sb = sbase + (s % 3) * 32768;
#pragma unroll
        for (int ks = 0; ks < 4; ks++) {
            unsigned a[4][4], bb[8][2];
#pragma unroll
            for (int mt = 0; mt < 4; mt++)
                ldsm4(a[mt][0], a[mt][1], a[mt][2], a[mt][3],
                      sb + offA[ks] + mt * 2048);
#pragma unroll
            for (int jg = 0; jg < 4; jg++)
                ldsm4(bb[2*jg][0], bb[2*jg][1], bb[2*jg+1][0], bb[2*jg+1][1],
                      sb + offB[ks] + jg * 2048);
#pragma unroll
            for (int mt = 0; mt < 4; mt++)
#pragma unroll
                for (int nt = 0; nt < 8; nt++)
                    mma16(c[mt][nt], a[mt], bb[nt]);
        }
        if (s + 2 < S) { issue(s + 2); CP_COMMIT(); }
    }

    const int rr2 = lane >> 2, cc = (lane & 3) * 2;
#pragma unroll
    for (int mt = 0; mt < 4; mt++) {
#pragma unroll
        for (int h2 = 0; h2 < 2; h2++) {
            int r = m0 + wm + mt * 16 + rr2 + h2 * 8;
            if (r >= M) continue;
            float wt; float* orow;
            if (moe) {
                int tok = g_idx[e * T_TOK + r];
                wt   = g_cw[e * T_TOK + r];
                orow = out + (size_t)tok * DDIM + n0 + wn;
            } else {
                wt   = g_sgate[r];
                orow = out + (size_t)r * DDIM + n0 + wn;
            }
#pragma unroll
            for (int nt = 0; nt < 8; nt++)
                red2(orow + nt * 8 + cc,
                     wt * c[mt][nt][2*h2+0], wt * c[mt][nt][2*h2+1]);
        }
    }
}

// ---------------- launch ----------------
extern "C" void kernel_launch(void* const* d_in, const int* in_sizes, int n_in,
                              void* d_out, int out_size) {
    const float* h    = (const float*)d_in[0];  // [T, D]
    const float* gw   = (const float*)d_in[1];  // [E, D]
    const float* gup  = (const float*)d_in[2];  // [E, 2I, D]
    const float* dwn  = (const float*)d_in[3];  // [E, D, I]
    const float* sgw  = (const float*)d_in[4];  // [IS, D]
    const float* suw  = (const float*)d_in[5];  // [IS, D]
    const float* sdw  = (const float*)d_in[6];  // [D, IS]
    const float* segw = (const float*)d_in[7];  // [1, D]
    float* out = (float*)d_out;

    const int SMEM = 98304;   // 96KB (3 x 32KB); 2 CTAs/SM = 192KB

    static bool init_done = false;
    if (!init_done) {
        cudaFuncSetAttribute(gateup_fused, cudaFuncAttributeMaxDynamicSharedMemorySize, SMEM);
        cudaFuncSetAttribute(down_fused,   cudaFuncAttributeMaxDynamicSharedMemorySize, SMEM);
        init_done = true;
    }

    // zero output (down_fused accumulates atomically into it)
    cudaMemsetAsync(out, 0, (size_t)out_size * sizeof(float));

    zero_cnt_kernel<<<1, 32>>>();

    // fused: fp16 conversion of h + all weights (y<6) and router (y==6)
    prep_kernel<<<dim3(T_TOK, 7), 256>>>(h, gup, dwn, sgw, suw, sdw, gw, segw);

    // fused gate/up (128 thr, 64x32x2 warp tiles): shared (0..2047) + MoE (2048..5119)
    gateup_fused<<<5120, 128, SMEM>>>();

    // fused down (128 thr, 64x64 warp tiles): shared (0..511) + MoE (512..4607)
    down_fused<<<4608, 128, SMEM>>>(out);
}